// round 13
// baseline (speedup 1.0000x reference)
#include <cuda_runtime.h>
#include <cuda_fp16.h>
#include <cstdint>

// SPIL layer, fused — sm_103-safe mma.sync.m16n8k16.f16.
// One CTA = 4 points (128 neighbor rows). 256 threads, 4 CTAs/SM (~42KB smem).
// Streaming loads use ld.global.cs (evict-first) so prepacked frag tables stay
// L1D-resident. r_l split 2 threads/row (masked rows via -1e30 encode).
// P2: theta MMA m32n32/warp + cf@phi_w MMA m16n16 on warps 4-7.
// Epilogue on tensor pipe: agg = W @ nf (ldmatrix.trans), out = agg @ z_w + sumW*z_b.

#define KNN 32
#define C_ 128
#define H_ 64

static constexpr int SAH_STR = 136;   // A stride in halves; LDSM conflict-free
static constexpr int SM_A    = 0;     // 128 x 136 fp16 = 34816 B
static constexpr int SM_CF   = 34816; // cf tile 16 x 136 fp16 (rows 0-3 valid) = 4352 B
static constexpr int SM_SCAL = 39168; // scalar float region
// float offsets inside scalar region
static constexpr int OF_FI  = 0;     // feat_i 4x64 (fp32); aggh (4x128 fp16) overlays in P5
static constexpr int OF_RFP = 256;   // rf partials per warp [8][32]
static constexpr int OF_RLP = 512;   // r_l partials 256 (2 per row; halves sum -> relu)
static constexpr int OF_W   = 768;   // W_ij as fp16 (128 halves)
static constexpr int OF_SW  = 832;   // sumW 4
static constexpr int SMEM_BYTES = SM_SCAL + 836 * 4;   // 42512 B -> 4 CTAs/SM

// merged lane-uniform weights: [0:96) m1_w, [96:128) m1_b, [128:224) m2_w,
// [224:256) m2_b, [256:320) psi_w, [320] psi_b
__constant__ float C_ALL[321];
#define C_M1W (C_ALL)
#define C_M1B (C_ALL + 96)
#define C_M2W (C_ALL + 128)
#define C_M2B (C_ALL + 224)
#define C_PSW (C_ALL + 256)
#define C_PSB (C_ALL + 320)

__device__ float  g_gather[321];   // staging for C_ALL (one DtoD memcpy node)
__device__ float4 g_Bh[1024];      // theta_w fp16 B-frags [kc][j(n16)][lane]
__device__ float4 g_Bp[1024];      // phi_w   fp16 B-frags, same layout
__device__ float2 g_Bz[2048];      // z_w     fp16 B-frags [kc][nt(n8)][lane]

__global__ void pack_weights(const float* __restrict__ theta_w,
                             const float* __restrict__ phi_w,
                             const float* __restrict__ z_w,
                             const float* __restrict__ m1_w, const float* __restrict__ m1_b,
                             const float* __restrict__ m2_w, const float* __restrict__ m2_b,
                             const float* __restrict__ psi_w, const float* __restrict__ psi_b) {
    int i = blockIdx.x * blockDim.x + threadIdx.x;
    if (i < 2048) {   // theta (0..1023) and phi (1024..2047), identical layout
        const float* src = (i < 1024) ? theta_w : phi_w;
        int ii = i & 1023;
        int lane = ii & 31, j = (ii >> 5) & 3, kc = ii >> 7;
        int g = lane >> 2, tg = lane & 3;
        int k0 = kc * 16 + 2 * tg;
        int n0 = j * 16 + g, n1 = n0 + 8;
        __half2 u0 = __floats2half2_rn(src[k0 * 64 + n0], src[(k0 + 1) * 64 + n0]);
        __half2 u1 = __floats2half2_rn(src[(k0 + 8) * 64 + n0], src[(k0 + 9) * 64 + n0]);
        __half2 u2 = __floats2half2_rn(src[k0 * 64 + n1], src[(k0 + 1) * 64 + n1]);
        __half2 u3 = __floats2half2_rn(src[(k0 + 8) * 64 + n1], src[(k0 + 9) * 64 + n1]);
        float4 v;
        v.x = __uint_as_float(*(uint32_t*)&u0);
        v.y = __uint_as_float(*(uint32_t*)&u1);
        v.z = __uint_as_float(*(uint32_t*)&u2);
        v.w = __uint_as_float(*(uint32_t*)&u3);
        if (i < 1024) g_Bh[ii] = v; else g_Bp[ii] = v;
    } else if (i < 4096) {   // z_w
        int j = i - 2048;
        int lane = j & 31, nt = (j >> 5) & 7, kc = j >> 8;
        int g = lane >> 2, tg = lane & 3;
        int k0 = kc * 16 + 2 * tg;
        int h = nt * 8 + g;
        __half2 u0 = __floats2half2_rn(z_w[k0 * 64 + h], z_w[(k0 + 1) * 64 + h]);
        __half2 u1 = __floats2half2_rn(z_w[(k0 + 8) * 64 + h], z_w[(k0 + 9) * 64 + h]);
        float2 v;
        v.x = __uint_as_float(*(uint32_t*)&u0);
        v.y = __uint_as_float(*(uint32_t*)&u1);
        g_Bz[j] = v;
    } else if (i < 4417) {   // gather lane-uniform weights
        int j = i - 4096;
        float v;
        if (j < 96)       v = m1_w[j];
        else if (j < 128) v = m1_b[j - 96];
        else if (j < 224) v = m2_w[j - 128];
        else if (j < 256) v = m2_b[j - 224];
        else if (j < 320) v = psi_w[j - 256];
        else              v = psi_b[0];
        g_gather[j] = v;
    }
}

__device__ __forceinline__ uint32_t smem_u32(const void* p) {
    uint32_t a;
    asm("{ .reg .u64 t; cvta.to.shared.u64 t, %1; cvt.u32.u64 %0, t; }" : "=r"(a) : "l"(p));
    return a;
}

__device__ __forceinline__ void mma_f16(float* d, uint32_t a0, uint32_t a1, uint32_t a2,
                                        uint32_t a3, uint32_t b0, uint32_t b1) {
    asm volatile(
        "mma.sync.aligned.m16n8k16.row.col.f32.f16.f16.f32 "
        "{%0,%1,%2,%3}, {%4,%5,%6,%7}, {%8,%9}, {%0,%1,%2,%3};"
        : "+f"(d[0]), "+f"(d[1]), "+f"(d[2]), "+f"(d[3])
        : "r"(a0), "r"(a1), "r"(a2), "r"(a3), "r"(b0), "r"(b1));
}

__global__ __launch_bounds__(256, 4)
void spil_kernel(const float* __restrict__ cxyz_g,  const float* __restrict__ cfeat_g,
                 const float* __restrict__ nxyz_g,  const float* __restrict__ nfeat_g,
                 const float* __restrict__ phi_b,   const float* __restrict__ theta_b,
                 const float* __restrict__ z_b,     float* __restrict__ out)
{
    extern __shared__ __align__(16) char smem[];
    float* sc = (float*)(smem + SM_SCAL);
    const uint32_t sbase = smem_u32(smem);
    const int tid = threadIdx.x;
    const int wid = tid >> 5, lid = tid & 31;
    const int g = lid >> 2, tg = lid & 3;
    const long g0 = (long)blockIdx.x * 4;

    // ================= P1: stage A (ldcs, STS.128) + r_l partials + cf ============
    {
        const float4* nf4 = (const float4*)(nfeat_g + g0 * (KNN * C_));
        #pragma unroll
        for (int it = 0; it < 8; it++) {
            int i = tid + it * 256;          // 0..2047
            float4 v0 = __ldcs(&nf4[2 * i]);         // evict-first: keep L1D for frags
            float4 v1 = __ldcs(&nf4[2 * i + 1]);
            int f = i << 3;
            int r = f >> 7, c = f & 127;     // c multiple of 8
            __half2 h0 = __floats2half2_rn(v0.x, v0.y);
            __half2 h1 = __floats2half2_rn(v0.z, v0.w);
            __half2 h2 = __floats2half2_rn(v1.x, v1.y);
            __half2 h3 = __floats2half2_rn(v1.z, v1.w);
            uint4 uv = make_uint4(*(uint32_t*)&h0, *(uint32_t*)&h1,
                                  *(uint32_t*)&h2, *(uint32_t*)&h3);
            *(uint4*)(smem + SM_A + (r * SAH_STR + c) * 2) = uv;
        }
    }
    {
        // r_l partial: 2 threads per neighbor row, 16 j-iters each (s_i half folded in).
        // Masked rows encoded by -1e30 on half 0; P4 does relu(v0+v1).
        const int r = tid >> 1, half = tid & 1, pp = r >> 5;
        const float* nx3 = nxyz_g + g0 * 96 + r * 3;
        float nx = nx3[0], ny = nx3[1], nz = nx3[2];
        float cx = cxyz_g[(g0 + pp) * 3], cy = cxyz_g[(g0 + pp) * 3 + 1],
              cz = cxyz_g[(g0 + pp) * 3 + 2];
        const int j0 = half * 16;
        float acc = half ? 0.f : C_PSB[0];
        #pragma unroll 8
        for (int j = j0; j < j0 + 16; j++) {
            float v = C_M1B[j] + cx * C_M1W[j] + cy * C_M1W[32 + j] + cz * C_M1W[64 + j];
            acc = fmaf(fmaxf(v, 0.f), C_PSW[j], acc);
        }
        #pragma unroll 8
        for (int j = j0; j < j0 + 16; j++) {
            float v = C_M2B[j] + nx * C_M2W[j] + ny * C_M2W[32 + j] + nz * C_M2W[64 + j];
            acc = fmaf(fmaxf(v, 0.f), C_PSW[32 + j], acc);
        }
        if (half == 0) {
            float dx = cx - nx, dy = cy - ny, dz = cz - nz;
            if (cz == nz && dx * dx + dy * dy + dz * dz > 0.0016f) acc -= 1e30f;  // SPIL mask
        }
        sc[OF_RLP + tid] = acc;
    }
    if (tid < 128) {
        // stage cf (4 rows x 128 cols fp16) into SM_CF rows 0-3
        int row = tid >> 5, c0 = (tid & 31) * 4;
        float4 v = __ldcs((const float4*)&cfeat_g[(g0 + row) * C_ + c0]);
        __half2 h0 = __floats2half2_rn(v.x, v.y);
        __half2 h1 = __floats2half2_rn(v.z, v.w);
        uint2 uv = make_uint2(*(uint32_t*)&h0, *(uint32_t*)&h1);
        *(uint2*)(smem + SM_CF + (row * SAH_STR + c0) * 2) = uv;
    }
    __syncthreads();

    // ================= P2: MMAs ===================================================
    const int p = wid >> 1, nh = wid & 1;

    // cf @ phi_w on warps 4-7 (m16n16 each)
    if (wid >= 4) {
        const int jt = wid - 4;      // n16 block 0..3
        float dcf[2][4];
        #pragma unroll
        for (int t = 0; t < 2; t++)
            #pragma unroll
            for (int j = 0; j < 4; j++) dcf[t][j] = 0.f;
        const uint32_t cfa = sbase + SM_CF
            + (uint32_t)((((lid & 15)) * SAH_STR + ((lid >> 4) * 8)) * 2);
        const float4* Bp = g_Bp + jt * 32 + lid;
        #pragma unroll
        for (int kc = 0; kc < 8; kc++) {
            uint32_t a0, a1, a2, a3;
            asm volatile("ldmatrix.sync.aligned.m8n8.x4.shared.b16 {%0,%1,%2,%3}, [%4];"
                         : "=r"(a0), "=r"(a1), "=r"(a2), "=r"(a3)
                         : "r"(cfa + (uint32_t)(kc * 32)));
            float4 bv = __ldg(Bp + kc * 128);
            mma_f16(dcf[0], a0, a1, a2, a3, __float_as_uint(bv.x), __float_as_uint(bv.y));
            mma_f16(dcf[1], a0, a1, a2, a3, __float_as_uint(bv.z), __float_as_uint(bv.w));
        }
        if (g < 4) {   // row g = point g; FI = relu(dcf + phi_b)
            #pragma unroll
            for (int t = 0; t < 2; t++) {
                int h0 = jt * 16 + t * 8 + 2 * tg;
                float2 pb = *(const float2*)&phi_b[h0];
                sc[OF_FI + g * 64 + h0]     = fmaxf(dcf[t][0] + pb.x, 0.f);
                sc[OF_FI + g * 64 + h0 + 1] = fmaxf(dcf[t][1] + pb.y, 0.f);
            }
        }
    }

    // theta MMA m32n32 (warp: point p, n-half nh) — all 8 warps
    float dacc[2][4][4];
    #pragma unroll
    for (int mt = 0; mt < 2; mt++)
        #pragma unroll
        for (int t = 0; t < 4; t++)
            #pragma unroll
            for (int j = 0; j < 4; j++) dacc[mt][t][j] = 0.f;
    {
        const uint32_t aa0 = sbase + SM_A
            + (uint32_t)(((p * 32 + (lid & 15)) * SAH_STR + ((lid >> 4) * 8)) * 2);
        const uint32_t aa1 = aa0 + (uint32_t)(16 * SAH_STR * 2);
        const float4* Bh0 = g_Bh + (2 * nh) * 32 + lid;
        const float4* Bh1 = Bh0 + 32;
        #pragma unroll
        for (int kc = 0; kc < 8; kc++) {
            uint32_t x0, x1, x2, x3, y0, y1, y2, y3;
            asm volatile("ldmatrix.sync.aligned.m8n8.x4.shared.b16 {%0,%1,%2,%3}, [%4];"
                         : "=r"(x0), "=r"(x1), "=r"(x2), "=r"(x3)
                         : "r"(aa0 + (uint32_t)(kc * 32)));
            asm volatile("ldmatrix.sync.aligned.m8n8.x4.shared.b16 {%0,%1,%2,%3}, [%4];"
                         : "=r"(y0), "=r"(y1), "=r"(y2), "=r"(y3)
                         : "r"(aa1 + (uint32_t)(kc * 32)));
            float4 bv0 = __ldg(Bh0 + kc * 128);
            float4 bv1 = __ldg(Bh1 + kc * 128);
            uint32_t b0 = __float_as_uint(bv0.x), b1 = __float_as_uint(bv0.y);
            uint32_t b2 = __float_as_uint(bv0.z), b3 = __float_as_uint(bv0.w);
            uint32_t b4 = __float_as_uint(bv1.x), b5 = __float_as_uint(bv1.y);
            uint32_t b6 = __float_as_uint(bv1.z), b7 = __float_as_uint(bv1.w);
            mma_f16(dacc[0][0], x0, x1, x2, x3, b0, b1);
            mma_f16(dacc[0][1], x0, x1, x2, x3, b2, b3);
            mma_f16(dacc[0][2], x0, x1, x2, x3, b4, b5);
            mma_f16(dacc[0][3], x0, x1, x2, x3, b6, b7);
            mma_f16(dacc[1][0], y0, y1, y2, y3, b0, b1);
            mma_f16(dacc[1][1], y0, y1, y2, y3, b2, b3);
            mma_f16(dacc[1][2], y0, y1, y2, y3, b4, b5);
            mma_f16(dacc[1][3], y0, y1, y2, y3, b6, b7);
        }
    }
    __syncthreads();   // FI ready for everyone

    // ================= P3: rf dot from dacc + FI; quad-reduce + transpose =========
    {
        float rfp[4] = {0.f, 0.f, 0.f, 0.f};
        #pragma unroll
        for (int t = 0; t < 4; t++) {
            int h0 = nh * 32 + t * 8 + 2 * tg;
            float2 fi = *(const float2*)&sc[OF_FI + p * 64 + h0];
            float2 tb = *(const float2*)&theta_b[h0];
            rfp[0] = fmaf(fi.x, fmaxf(dacc[0][t][0] + tb.x, 0.f),
                     fmaf(fi.y, fmaxf(dacc[0][t][1] + tb.y, 0.f), rfp[0]));
            rfp[1] = fmaf(fi.x, fmaxf(dacc[0][t][2] + tb.x, 0.f),
                     fmaf(fi.y, fmaxf(dacc[0][t][3] + tb.y, 0.f), rfp[1]));
            rfp[2] = fmaf(fi.x, fmaxf(dacc[1][t][0] + tb.x, 0.f),
                     fmaf(fi.y, fmaxf(dacc[1][t][1] + tb.y, 0.f), rfp[2]));
            rfp[3] = fmaf(fi.x, fmaxf(dacc[1][t][2] + tb.x, 0.f),
                     fmaf(fi.y, fmaxf(dacc[1][t][3] + tb.y, 0.f), rfp[3]));
        }
        #pragma unroll
        for (int j = 0; j < 4; j++) {
            rfp[j] += __shfl_xor_sync(0xFFFFFFFFu, rfp[j], 1);
            rfp[j] += __shfl_xor_sync(0xFFFFFFFFu, rfp[j], 2);
        }
        sc[OF_RFP + wid * 32 + g + 8 * tg] = rfp[tg];
    }
    __syncthreads();

    // ================= P4: softmax (warps 0-3), W stored as fp16 ==================
    __half* Wh = (__half*)(sc + OF_W);
    if (wid < 4) {
        const int k = lid, r = wid * KNN + k;
        float rf = (sc[OF_RFP + (2 * wid) * 32 + k] + sc[OF_RFP + (2 * wid + 1) * 32 + k])
                 * 0.125f;   // 1/sqrt(H)
        float2 rlv = *(const float2*)&sc[OF_RLP + 2 * r];
        float rl = fmaxf(rlv.x + rlv.y, 0.f);   // masked rows: -1e30 encode -> 0
        float m = rf;
        #pragma unroll
        for (int o = 16; o; o >>= 1) m = fmaxf(m, __shfl_xor_sync(0xFFFFFFFFu, m, o));
        float e = rl * __expf(rf - m);
        float s = e;
        #pragma unroll
        for (int o = 16; o; o >>= 1) s += __shfl_xor_sync(0xFFFFFFFFu, s, o);
        float inv = 1.f / (s + 1e-8f);
        Wh[r] = __float2half(e * inv);
        if (k == 0) sc[OF_SW + wid] = s * inv;
    }
    __syncthreads();

    // ================= P5: MMA-2  agg[4,128] = W @ nf-tile ========================
    __half* aggh = (__half*)(sc + OF_FI);  // FI dead after P3
    {
        float d2[2][4];
        #pragma unroll
        for (int t = 0; t < 2; t++)
            #pragma unroll
            for (int j = 0; j < 4; j++) d2[t][j] = 0.f;
        const int row_l = ((lid >> 3) & 1) * 8 + (lid & 7);
        const uint32_t baddr = sbase + SM_A
            + (uint32_t)((row_l * SAH_STR + wid * 16 + (lid >> 4) * 8) * 2);
        #pragma unroll
        for (int kc = 0; kc < 8; kc++) {
            uint32_t b0, b1, b2, b3;
            asm volatile("ldmatrix.sync.aligned.m8n8.x4.trans.shared.b16 {%0,%1,%2,%3}, [%4];"
                         : "=r"(b0), "=r"(b1), "=r"(b2), "=r"(b3)
                         : "r"(baddr + (uint32_t)(kc * 16 * SAH_STR * 2)));
            uint32_t a0 = 0u, a2 = 0u;
            if (g == (kc >> 1)) {
                const __half* wp = Wh + g * 32 + (kc & 1) * 16 + 2 * tg;
                a0 = *(const uint32_t*)wp;
                a2 = *(const uint32_t*)(wp + 8);
            }
            mma_f16(d2[0], a0, 0u, a2, 0u, b0, b1);
            mma_f16(d2[1], a0, 0u, a2, 0u, b2, b3);
        }
        if (g < 4) {
            #pragma unroll
            for (int t = 0; t < 2; t++) {
                __half2 hv = __floats2half2_rn(d2[t][0], d2[t][1]);
                *(uint32_t*)&aggh[g * 128 + wid * 16 + t * 8 + 2 * tg] = *(uint32_t*)&hv;
            }
        }
    }
    __syncthreads();

    // ================= P6: MMA-3  out[4,64] = agg @ z_w  (+ sumW*z_b) =============
    {
        float d3[4] = {0.f, 0.f, 0.f, 0.f};
        const float2* Bz = g_Bz + wid * 32 + lid;
        #pragma unroll
        for (int kc = 0; kc < 8; kc++) {
            uint32_t a0 = 0u, a2 = 0u;
            if (g < 4) {
                const __half* ap = aggh + g * 128 + kc * 16 + 2 * tg;
                a0 = *(const uint32_t*)ap;
                a2 = *(const uint32_t*)(ap + 8);
            }
            float2 bv = __ldg(Bz + kc * 256);
            mma_f16(d3, a0, 0u, a2, 0u, __float_as_uint(bv.x), __float_as_uint(bv.y));
        }
        if (g < 4) {
            int h0 = wid * 8 + 2 * tg;
            float sw = sc[OF_SW + g];
            float2 o;
            o.x = d3[0] + sw * z_b[h0];
            o.y = d3[1] + sw * z_b[h0 + 1];
            *(float2*)&out[(g0 + g) * H_ + h0] = o;
        }
    }
}

extern "C" void kernel_launch(void* const* d_in, const int* in_sizes, int n_in,
                              void* d_out, int out_size) {
    (void)in_sizes; (void)n_in; (void)out_size;
    cudaFuncSetAttribute(spil_kernel, cudaFuncAttributeMaxDynamicSharedMemorySize, SMEM_BYTES);

    pack_weights<<<18, 256>>>(
        (const float*)d_in[6],  (const float*)d_in[4],  (const float*)d_in[14],
        (const float*)d_in[8],  (const float*)d_in[9],
        (const float*)d_in[10], (const float*)d_in[11],
        (const float*)d_in[12], (const float*)d_in[13]);

    void *dstc, *srcg;
    cudaGetSymbolAddress(&dstc, C_ALL);
    cudaGetSymbolAddress(&srcg, g_gather);
    cudaMemcpyAsync(dstc, srcg, 321 * 4, cudaMemcpyDeviceToDevice);

    spil_kernel<<<8192, 256, SMEM_BYTES>>>(
        (const float*)d_in[0], (const float*)d_in[1],
        (const float*)d_in[2], (const float*)d_in[3],
        (const float*)d_in[5], (const float*)d_in[7],
        (const float*)d_in[15],
        (float*)d_out);
}

// round 14
// speedup vs baseline: 1.0177x; 1.0177x over previous
#include <cuda_runtime.h>
#include <cuda_fp16.h>
#include <cstdint>

// SPIL layer, fused — sm_103-safe mma.sync.m16n8k16.f16.
// One CTA = 4 points (128 neighbor rows). 256 threads, 4 CTAs/SM (~42KB smem).
// P2: theta MMA m32n32/warp (all 8) + cf@phi_w MMA m16n16 spread over warps 4-7.
// Epilogue on tensor pipe: agg = W @ nf (ldmatrix.trans), out = agg @ z_w + sumW*z_b.
// Round 14: revert round-13 (ldcs / r_l split); add P5 W-frag preload (branch-free)
// and Bz prefetch across the P5->P6 barrier.

#define KNN 32
#define C_ 128
#define H_ 64

static constexpr int SAH_STR = 136;   // A stride in halves; LDSM conflict-free
static constexpr int SM_A    = 0;     // 128 x 136 fp16 = 34816 B
static constexpr int SM_CF   = 34816; // cf tile 16 x 136 fp16 (rows 0-3 valid) = 4352 B
static constexpr int SM_SCAL = 39168; // scalar float region
// float offsets inside scalar region
static constexpr int OF_FI  = 0;     // feat_i 4x64 (fp32); aggh (4x128 fp16) overlays in P5
static constexpr int OF_RFP = 256;   // rf partials per warp [8][32]
static constexpr int OF_RL  = 512;   // r_l (masked) 128
static constexpr int OF_W   = 640;   // W_ij as fp16 (128 halves)
static constexpr int OF_SW  = 704;   // sumW 4
static constexpr int SMEM_BYTES = SM_SCAL + 708 * 4;   // 42000 B -> 4 CTAs/SM

// merged lane-uniform weights: [0:96) m1_w, [96:128) m1_b, [128:224) m2_w,
// [224:256) m2_b, [256:320) psi_w, [320] psi_b
__constant__ float C_ALL[321];
#define C_M1W (C_ALL)
#define C_M1B (C_ALL + 96)
#define C_M2W (C_ALL + 128)
#define C_M2B (C_ALL + 224)
#define C_PSW (C_ALL + 256)
#define C_PSB (C_ALL + 320)

__device__ float  g_gather[321];   // staging for C_ALL (one DtoD memcpy node)
__device__ float4 g_Bh[1024];      // theta_w fp16 B-frags [kc][j(n16)][lane]
__device__ float4 g_Bp[1024];      // phi_w   fp16 B-frags, same layout
__device__ float2 g_Bz[2048];      // z_w     fp16 B-frags [kc][nt(n8)][lane]

__global__ void pack_weights(const float* __restrict__ theta_w,
                             const float* __restrict__ phi_w,
                             const float* __restrict__ z_w,
                             const float* __restrict__ m1_w, const float* __restrict__ m1_b,
                             const float* __restrict__ m2_w, const float* __restrict__ m2_b,
                             const float* __restrict__ psi_w, const float* __restrict__ psi_b) {
    int i = blockIdx.x * blockDim.x + threadIdx.x;
    if (i < 2048) {   // theta (0..1023) and phi (1024..2047), identical layout
        const float* src = (i < 1024) ? theta_w : phi_w;
        int ii = i & 1023;
        int lane = ii & 31, j = (ii >> 5) & 3, kc = ii >> 7;
        int g = lane >> 2, tg = lane & 3;
        int k0 = kc * 16 + 2 * tg;
        int n0 = j * 16 + g, n1 = n0 + 8;
        __half2 u0 = __floats2half2_rn(src[k0 * 64 + n0], src[(k0 + 1) * 64 + n0]);
        __half2 u1 = __floats2half2_rn(src[(k0 + 8) * 64 + n0], src[(k0 + 9) * 64 + n0]);
        __half2 u2 = __floats2half2_rn(src[k0 * 64 + n1], src[(k0 + 1) * 64 + n1]);
        __half2 u3 = __floats2half2_rn(src[(k0 + 8) * 64 + n1], src[(k0 + 9) * 64 + n1]);
        float4 v;
        v.x = __uint_as_float(*(uint32_t*)&u0);
        v.y = __uint_as_float(*(uint32_t*)&u1);
        v.z = __uint_as_float(*(uint32_t*)&u2);
        v.w = __uint_as_float(*(uint32_t*)&u3);
        if (i < 1024) g_Bh[ii] = v; else g_Bp[ii] = v;
    } else if (i < 4096) {   // z_w
        int j = i - 2048;
        int lane = j & 31, nt = (j >> 5) & 7, kc = j >> 8;
        int g = lane >> 2, tg = lane & 3;
        int k0 = kc * 16 + 2 * tg;
        int h = nt * 8 + g;
        __half2 u0 = __floats2half2_rn(z_w[k0 * 64 + h], z_w[(k0 + 1) * 64 + h]);
        __half2 u1 = __floats2half2_rn(z_w[(k0 + 8) * 64 + h], z_w[(k0 + 9) * 64 + h]);
        float2 v;
        v.x = __uint_as_float(*(uint32_t*)&u0);
        v.y = __uint_as_float(*(uint32_t*)&u1);
        g_Bz[j] = v;
    } else if (i < 4417) {   // gather lane-uniform weights
        int j = i - 4096;
        float v;
        if (j < 96)       v = m1_w[j];
        else if (j < 128) v = m1_b[j - 96];
        else if (j < 224) v = m2_w[j - 128];
        else if (j < 256) v = m2_b[j - 224];
        else if (j < 320) v = psi_w[j - 256];
        else              v = psi_b[0];
        g_gather[j] = v;
    }
}

__device__ __forceinline__ uint32_t smem_u32(const void* p) {
    uint32_t a;
    asm("{ .reg .u64 t; cvta.to.shared.u64 t, %1; cvt.u32.u64 %0, t; }" : "=r"(a) : "l"(p));
    return a;
}

__device__ __forceinline__ void mma_f16(float* d, uint32_t a0, uint32_t a1, uint32_t a2,
                                        uint32_t a3, uint32_t b0, uint32_t b1) {
    asm volatile(
        "mma.sync.aligned.m16n8k16.row.col.f32.f16.f16.f32 "
        "{%0,%1,%2,%3}, {%4,%5,%6,%7}, {%8,%9}, {%0,%1,%2,%3};"
        : "+f"(d[0]), "+f"(d[1]), "+f"(d[2]), "+f"(d[3])
        : "r"(a0), "r"(a1), "r"(a2), "r"(a3), "r"(b0), "r"(b1));
}

__global__ __launch_bounds__(256, 4)
void spil_kernel(const float* __restrict__ cxyz_g,  const float* __restrict__ cfeat_g,
                 const float* __restrict__ nxyz_g,  const float* __restrict__ nfeat_g,
                 const float* __restrict__ phi_b,   const float* __restrict__ theta_b,
                 const float* __restrict__ z_b,     float* __restrict__ out)
{
    extern __shared__ __align__(16) char smem[];
    float* sc = (float*)(smem + SM_SCAL);
    const uint32_t sbase = smem_u32(smem);
    const int tid = threadIdx.x;
    const int wid = tid >> 5, lid = tid & 31;
    const int g = lid >> 2, tg = lid & 3;
    const long g0 = (long)blockIdx.x * 4;

    // ================= P1: stage A (8 halves/thread, STS.128) + cf + r_l ==========
    {
        const float4* nf4 = (const float4*)(nfeat_g + g0 * (KNN * C_));
        #pragma unroll
        for (int it = 0; it < 8; it++) {
            int i = tid + it * 256;          // 0..2047
            float4 v0 = nf4[2 * i];
            float4 v1 = nf4[2 * i + 1];
            int f = i << 3;
            int r = f >> 7, c = f & 127;     // c multiple of 8
            __half2 h0 = __floats2half2_rn(v0.x, v0.y);
            __half2 h1 = __floats2half2_rn(v0.z, v0.w);
            __half2 h2 = __floats2half2_rn(v1.x, v1.y);
            __half2 h3 = __floats2half2_rn(v1.z, v1.w);
            uint4 uv = make_uint4(*(uint32_t*)&h0, *(uint32_t*)&h1,
                                  *(uint32_t*)&h2, *(uint32_t*)&h3);
            *(uint4*)(smem + SM_A + (r * SAH_STR + c) * 2) = uv;
        }
    }
    if (tid < 128) {
        // r_l for neighbor row r, s_i inline (all const-bank math)
        const int r = tid, pp = r >> 5;
        float nx = nxyz_g[g0 * 96 + r * 3], ny = nxyz_g[g0 * 96 + r * 3 + 1],
              nz = nxyz_g[g0 * 96 + r * 3 + 2];
        float cx = cxyz_g[(g0 + pp) * 3], cy = cxyz_g[(g0 + pp) * 3 + 1],
              cz = cxyz_g[(g0 + pp) * 3 + 2];
        float acc = C_PSB[0];
        #pragma unroll 8
        for (int j = 0; j < 32; j++) {
            float v = C_M1B[j] + cx * C_M1W[j] + cy * C_M1W[32 + j] + cz * C_M1W[64 + j];
            acc = fmaf(fmaxf(v, 0.f), C_PSW[j], acc);
        }
        #pragma unroll 8
        for (int j = 0; j < 32; j++) {
            float v = C_M2B[j] + nx * C_M2W[j] + ny * C_M2W[32 + j] + nz * C_M2W[64 + j];
            acc = fmaf(fmaxf(v, 0.f), C_PSW[32 + j], acc);
        }
        float rl = fmaxf(acc, 0.f);
        float dx = cx - nx, dy = cy - ny, dz = cz - nz;
        if (cz == nz && dx * dx + dy * dy + dz * dz > 0.0016f) rl = 0.f;  // SPIL mask
        sc[OF_RL + r] = rl;
    } else {
        // stage cf (4 rows x 128 cols fp16) into SM_CF rows 0-3
        int i = tid - 128;           // 0..127
        int row = i >> 5, c0 = (i & 31) * 4;
        float4 v = *(const float4*)&cfeat_g[(g0 + row) * C_ + c0];
        __half2 h0 = __floats2half2_rn(v.x, v.y);
        __half2 h1 = __floats2half2_rn(v.z, v.w);
        uint2 uv = make_uint2(*(uint32_t*)&h0, *(uint32_t*)&h1);
        *(uint2*)(smem + SM_CF + (row * SAH_STR + c0) * 2) = uv;
    }
    __syncthreads();

    // ================= P2: MMAs ===================================================
    const int p = wid >> 1, nh = wid & 1;

    // cf @ phi_w on warps 4-7 (m16n16 each): extra load 12.5%/warp
    if (wid >= 4) {
        const int jt = wid - 4;      // n16 block 0..3
        float dcf[2][4];
        #pragma unroll
        for (int t = 0; t < 2; t++)
            #pragma unroll
            for (int j = 0; j < 4; j++) dcf[t][j] = 0.f;
        const uint32_t cfa = sbase + SM_CF
            + (uint32_t)((((lid & 15)) * SAH_STR + ((lid >> 4) * 8)) * 2);
        const float4* Bp = g_Bp + jt * 32 + lid;
        #pragma unroll
        for (int kc = 0; kc < 8; kc++) {
            uint32_t a0, a1, a2, a3;
            asm volatile("ldmatrix.sync.aligned.m8n8.x4.shared.b16 {%0,%1,%2,%3}, [%4];"
                         : "=r"(a0), "=r"(a1), "=r"(a2), "=r"(a3)
                         : "r"(cfa + (uint32_t)(kc * 32)));
            float4 bv = __ldg(Bp + kc * 128);
            mma_f16(dcf[0], a0, a1, a2, a3, __float_as_uint(bv.x), __float_as_uint(bv.y));
            mma_f16(dcf[1], a0, a1, a2, a3, __float_as_uint(bv.z), __float_as_uint(bv.w));
        }
        if (g < 4) {   // row g = point g; FI = relu(dcf + phi_b)
            #pragma unroll
            for (int t = 0; t < 2; t++) {
                int h0 = jt * 16 + t * 8 + 2 * tg;
                float2 pb = *(const float2*)&phi_b[h0];
                sc[OF_FI + g * 64 + h0]     = fmaxf(dcf[t][0] + pb.x, 0.f);
                sc[OF_FI + g * 64 + h0 + 1] = fmaxf(dcf[t][1] + pb.y, 0.f);
            }
        }
    }

    // theta MMA m32n32 (warp: point p, n-half nh) — all 8 warps
    float dacc[2][4][4];
    #pragma unroll
    for (int mt = 0; mt < 2; mt++)
        #pragma unroll
        for (int t = 0; t < 4; t++)
            #pragma unroll
            for (int j = 0; j < 4; j++) dacc[mt][t][j] = 0.f;
    {
        const uint32_t aa0 = sbase + SM_A
            + (uint32_t)(((p * 32 + (lid & 15)) * SAH_STR + ((lid >> 4) * 8)) * 2);
        const uint32_t aa1 = aa0 + (uint32_t)(16 * SAH_STR * 2);
        const float4* Bh0 = g_Bh + (2 * nh) * 32 + lid;
        const float4* Bh1 = Bh0 + 32;
        #pragma unroll
        for (int kc = 0; kc < 8; kc++) {
            uint32_t x0, x1, x2, x3, y0, y1, y2, y3;
            asm volatile("ldmatrix.sync.aligned.m8n8.x4.shared.b16 {%0,%1,%2,%3}, [%4];"
                         : "=r"(x0), "=r"(x1), "=r"(x2), "=r"(x3)
                         : "r"(aa0 + (uint32_t)(kc * 32)));
            asm volatile("ldmatrix.sync.aligned.m8n8.x4.shared.b16 {%0,%1,%2,%3}, [%4];"
                         : "=r"(y0), "=r"(y1), "=r"(y2), "=r"(y3)
                         : "r"(aa1 + (uint32_t)(kc * 32)));
            float4 bv0 = __ldg(Bh0 + kc * 128);
            float4 bv1 = __ldg(Bh1 + kc * 128);
            uint32_t b0 = __float_as_uint(bv0.x), b1 = __float_as_uint(bv0.y);
            uint32_t b2 = __float_as_uint(bv0.z), b3 = __float_as_uint(bv0.w);
            uint32_t b4 = __float_as_uint(bv1.x), b5 = __float_as_uint(bv1.y);
            uint32_t b6 = __float_as_uint(bv1.z), b7 = __float_as_uint(bv1.w);
            mma_f16(dacc[0][0], x0, x1, x2, x3, b0, b1);
            mma_f16(dacc[0][1], x0, x1, x2, x3, b2, b3);
            mma_f16(dacc[0][2], x0, x1, x2, x3, b4, b5);
            mma_f16(dacc[0][3], x0, x1, x2, x3, b6, b7);
            mma_f16(dacc[1][0], y0, y1, y2, y3, b0, b1);
            mma_f16(dacc[1][1], y0, y1, y2, y3, b2, b3);
            mma_f16(dacc[1][2], y0, y1, y2, y3, b4, b5);
            mma_f16(dacc[1][3], y0, y1, y2, y3, b6, b7);
        }
    }
    __syncthreads();   // FI ready for everyone

    // ================= P3: rf dot from dacc + FI; quad-reduce + transpose =========
    {
        float rfp[4] = {0.f, 0.f, 0.f, 0.f};
        #pragma unroll
        for (int t = 0; t < 4; t++) {
            int h0 = nh * 32 + t * 8 + 2 * tg;
            float2 fi = *(const float2*)&sc[OF_FI + p * 64 + h0];
            float2 tb = *(const float2*)&theta_b[h0];
            rfp[0] = fmaf(fi.x, fmaxf(dacc[0][t][0] + tb.x, 0.f),
                     fmaf(fi.y, fmaxf(dacc[0][t][1] + tb.y, 0.f), rfp[0]));
            rfp[1] = fmaf(fi.x, fmaxf(dacc[0][t][2] + tb.x, 0.f),
                     fmaf(fi.y, fmaxf(dacc[0][t][3] + tb.y, 0.f), rfp[1]));
            rfp[2] = fmaf(fi.x, fmaxf(dacc[1][t][0] + tb.x, 0.f),
                     fmaf(fi.y, fmaxf(dacc[1][t][1] + tb.y, 0.f), rfp[2]));
            rfp[3] = fmaf(fi.x, fmaxf(dacc[1][t][2] + tb.x, 0.f),
                     fmaf(fi.y, fmaxf(dacc[1][t][3] + tb.y, 0.f), rfp[3]));
        }
        #pragma unroll
        for (int j = 0; j < 4; j++) {
            rfp[j] += __shfl_xor_sync(0xFFFFFFFFu, rfp[j], 1);
            rfp[j] += __shfl_xor_sync(0xFFFFFFFFu, rfp[j], 2);
        }
        sc[OF_RFP + wid * 32 + g + 8 * tg] = rfp[tg];
    }
    __syncthreads();

    // ================= P4: softmax (warps 0-3), W stored as fp16 ==================
    __half* Wh = (__half*)(sc + OF_W);
    if (wid < 4) {
        const int k = lid, r = wid * KNN + k;
        float rf = (sc[OF_RFP + (2 * wid) * 32 + k] + sc[OF_RFP + (2 * wid + 1) * 32 + k])
                 * 0.125f;   // 1/sqrt(H)
        float rl = sc[OF_RL + r];
        float m = rf;
        #pragma unroll
        for (int o = 16; o; o >>= 1) m = fmaxf(m, __shfl_xor_sync(0xFFFFFFFFu, m, o));
        float e = rl * __expf(rf - m);
        float s = e;
        #pragma unroll
        for (int o = 16; o; o >>= 1) s += __shfl_xor_sync(0xFFFFFFFFu, s, o);
        float inv = 1.f / (s + 1e-8f);
        Wh[r] = __float2half(e * inv);
        if (k == 0) sc[OF_SW + wid] = s * inv;
    }
    __syncthreads();

    // ================= P5: MMA-2  agg[4,128] = W @ nf-tile ========================
    __half* aggh = (__half*)(sc + OF_FI);  // FI dead after P3
    const float2* Bz = g_Bz + wid * 32 + lid;
    {
        float d2[2][4];
        #pragma unroll
        for (int t = 0; t < 2; t++)
            #pragma unroll
            for (int j = 0; j < 4; j++) d2[t][j] = 0.f;
        // branch-free W preload: 4 regs, loaded once (only g<4 lanes ever contribute)
        uint32_t wE0 = 0u, wE2 = 0u, wO0 = 0u, wO2 = 0u;
        if (g < 4) {
            const __half* wp = Wh + g * 32 + 2 * tg;
            wE0 = *(const uint32_t*)wp;          // kc even: +0, +8
            wE2 = *(const uint32_t*)(wp + 8);
            wO0 = *(const uint32_t*)(wp + 16);   // kc odd:  +16, +24
            wO2 = *(const uint32_t*)(wp + 24);
        }
        const int row_l = ((lid >> 3) & 1) * 8 + (lid & 7);
        const uint32_t baddr = sbase + SM_A
            + (uint32_t)((row_l * SAH_STR + wid * 16 + (lid >> 4) * 8) * 2);
        #pragma unroll
        for (int kc = 0; kc < 8; kc++) {
            uint32_t b0, b1, b2, b3;
            asm volatile("ldmatrix.sync.aligned.m8n8.x4.trans.shared.b16 {%0,%1,%2,%3}, [%4];"
                         : "=r"(b0), "=r"(b1), "=r"(b2), "=r"(b3)
                         : "r"(baddr + (uint32_t)(kc * 16 * SAH_STR * 2)));
            uint32_t a0 = 0u, a2 = 0u;
            if (g == (kc >> 1)) {
                a0 = (kc & 1) ? wO0 : wE0;
                a2 = (kc & 1) ? wO2 : wE2;
            }
            mma_f16(d2[0], a0, 0u, a2, 0u, b0, b1);
            mma_f16(d2[1], a0, 0u, a2, 0u, b2, b3);
        }
        if (g < 4) {
            #pragma unroll
            for (int t = 0; t < 2; t++) {
                __half2 hv = __floats2half2_rn(d2[t][0], d2[t][1]);
                *(uint32_t*)&aggh[g * 128 + wid * 16 + t * 8 + 2 * tg] = *(uint32_t*)&hv;
            }
        }
    }
    // prefetch z-fragments: LDG latency absorbed by the barrier wait below
    float2 bz[8];
    #pragma unroll
    for (int kc = 0; kc < 8; kc++) bz[kc] = __ldg(Bz + kc * 256);
    __syncthreads();

    // ================= P6: MMA-3  out[4,64] = agg @ z_w  (+ sumW*z_b) =============
    {
        float d3[4] = {0.f, 0.f, 0.f, 0.f};
        #pragma unroll
        for (int kc = 0; kc < 8; kc++) {
            uint32_t a0 = 0u, a2 = 0u;
            if (g < 4) {
                const __half* ap = aggh + g * 128 + kc * 16 + 2 * tg;
                a0 = *(const uint32_t*)ap;
                a2 = *(const uint32_t*)(ap + 8);
            }
            mma_f16(d3, a0, 0u, a2, 0u,
                    __float_as_uint(bz[kc].x), __float_as_uint(bz[kc].y));
        }
        if (g < 4) {
            int h0 = wid * 8 + 2 * tg;
            float sw = sc[OF_SW + g];
            float2 o;
            o.x = d3[0] + sw * z_b[h0];
            o.y = d3[1] + sw * z_b[h0 + 1];
            *(float2*)&out[(g0 + g) * H_ + h0] = o;
        }
    }
}

extern "C" void kernel_launch(void* const* d_in, const int* in_sizes, int n_in,
                              void* d_out, int out_size) {
    (void)in_sizes; (void)n_in; (void)out_size;
    cudaFuncSetAttribute(spil_kernel, cudaFuncAttributeMaxDynamicSharedMemorySize, SMEM_BYTES);

    pack_weights<<<18, 256>>>(
        (const float*)d_in[6],  (const float*)d_in[4],  (const float*)d_in[14],
        (const float*)d_in[8],  (const float*)d_in[9],
        (const float*)d_in[10], (const float*)d_in[11],
        (const float*)d_in[12], (const float*)d_in[13]);

    void *dstc, *srcg;
    cudaGetSymbolAddress(&dstc, C_ALL);
    cudaGetSymbolAddress(&srcg, g_gather);
    cudaMemcpyAsync(dstc, srcg, 321 * 4, cudaMemcpyDeviceToDevice);

    spil_kernel<<<8192, 256, SMEM_BYTES>>>(
        (const float*)d_in[0], (const float*)d_in[1],
        (const float*)d_in[2], (const float*)d_in[3],
        (const float*)d_in[5], (const float*)d_in[7],
        (const float*)d_in[15],
        (float*)d_out);
}